// round 8
// baseline (speedup 1.0000x reference)
#include <cuda_runtime.h>
#include <cuda_fp16.h>
#include <cstdint>

// MLP3D_final — mma.sync HMMA with f16 ACCUMULATORS (rate test), promoted to
// fp32 registers every K=32 (2 chained f16-acc MMAs -> unpack-add).
// Structure otherwise identical to R5: 512 thr (16 warps, 4x4), K-chunked
// double-buffered weight staging, warp tile 32x64.

#define THREADS 512

// strides in f16 elements
#define SA 264   // activation rows (256 + 8 pad)
#define SE 72    // embedding rows (64 + 8 pad)
#define SW 72    // small weight images (k=64)
#define SC 136   // big-weight chunk images (k=128 + 8 pad)

#define CHUNK_BYTES (256 * SC * 2)   // 69632
#define SMALL_BYTES (256 * SW * 2)   // 36864

// smem byte offsets
#define OFF_WB0 0
#define OFF_WB1 69632
#define OFF_X   139264
#define OFF_PAR 206848
#define OFF_OCC 212032
#define SMEM_BYTES 214080

// param vector layout (floats)
#define PB0 0
#define PB1 256
#define PB2 512
#define PWC 768
#define PWOCC 1024
#define PBC 1280
#define PBOCC 1284
#define NPAR 1285

__device__ __align__(16) unsigned char gW0t[SMALL_BYTES];
__device__ __align__(16) unsigned char gW1bd[SMALL_BYTES];
__device__ __align__(16) unsigned char gW1t[2 * CHUNK_BYTES];
__device__ __align__(16) unsigned char gW2t[2 * CHUNK_BYTES];
__device__ float gParams[NPAR];

// ---------------- PTX helpers ----------------
__device__ __forceinline__ uint32_t smem_u32(const void* p) {
    uint32_t a;
    asm("{ .reg .u64 t; cvta.to.shared.u64 t, %1; cvt.u32.u64 %0, t; }" : "=r"(a) : "l"(p));
    return a;
}
__device__ __forceinline__ void ldmx4(uint32_t* r, uint32_t a) {
    asm volatile("ldmatrix.sync.aligned.m8n8.x4.shared.b16 {%0,%1,%2,%3}, [%4];"
                 : "=r"(r[0]), "=r"(r[1]), "=r"(r[2]), "=r"(r[3]) : "r"(a));
}
// f16-accumulator HMMA: D(f16x2 pair) += A x B
__device__ __forceinline__ void mma_h(uint32_t& d0, uint32_t& d1,
                                      const uint32_t* a, uint32_t b0, uint32_t b1) {
    asm volatile(
        "mma.sync.aligned.m16n8k16.row.col.f16.f16.f16.f16 "
        "{%0,%1}, {%2,%3,%4,%5}, {%6,%7}, {%0,%1};"
        : "+r"(d0), "+r"(d1)
        : "r"(a[0]), "r"(a[1]), "r"(a[2]), "r"(a[3]), "r"(b0), "r"(b1));
}
// two chained f16-acc MMAs (K=32) then promote into fp32 accumulators
__device__ __forceinline__ void mma2_promote(float* c,
                                             const uint32_t* ak0, const uint32_t* ak1,
                                             uint32_t b00, uint32_t b01,
                                             uint32_t b10, uint32_t b11) {
    uint32_t d0 = 0, d1 = 0;
    mma_h(d0, d1, ak0, b00, b01);
    mma_h(d0, d1, ak1, b10, b11);
    const float2 f0 = __half22float2(*reinterpret_cast<__half2*>(&d0));
    const float2 f1 = __half22float2(*reinterpret_cast<__half2*>(&d1));
    c[0] += f0.x; c[1] += f0.y; c[2] += f1.x; c[3] += f1.y;
}
__device__ __forceinline__ void cp16(uint32_t dst, const void* src) {
    asm volatile("cp.async.cg.shared.global [%0], [%1], 16;" :: "r"(dst), "l"(src));
}
#define CP_COMMIT() asm volatile("cp.async.commit_group;" ::: "memory")
#define CP_WAIT(n)  asm volatile("cp.async.wait_group %0;" :: "n"(n) : "memory")

// ---------------- prep kernel ----------------
__global__ void prep_kernel(
    const float* __restrict__ W0, const float* __restrict__ b0,
    const float* __restrict__ W1, const float* __restrict__ b1,
    const float* __restrict__ W2, const float* __restrict__ b2,
    const float* __restrict__ Wocc, const float* __restrict__ bocc,
    const float* __restrict__ Wc, const float* __restrict__ bc)
{
    const int idx = blockIdx.x * blockDim.x + threadIdx.x;
    const int stride = gridDim.x * blockDim.x;
    for (int i = idx; i < 256 * 320; i += stride) {
        const int n = i & 255;
        const int t = i >> 8;
        if (t < 32) {                                   // W0t [n][k<64]
            const int k = t * 2;
            const float v0 = (k < 63) ? W0[k * 256 + n] : 0.f;
            const float v1 = (k + 1 < 63) ? W0[(k + 1) * 256 + n] : 0.f;
            __half2 h = __floats2half2_rn(v0, v1);
            *(uint32_t*)(gW0t + (n * SW + k) * 2) = *(uint32_t*)&h;
        } else if (t < 64) {                            // W1bdT diag blocks
            const int k = (t - 32) * 2;
            const int base = (n >> 6) * 64;
            __half2 h = __floats2half2_rn(W1[(base + k) * 256 + n],
                                          W1[(base + k + 1) * 256 + n]);
            *(uint32_t*)(gW1bd + (n * SW + k) * 2) = *(uint32_t*)&h;
        } else if (t < 192) {                           // W1t chunked
            const int k = (t - 64) * 2;
            const int c = k >> 7, kk = k & 127;
            __half2 h = __floats2half2_rn(W1[k * 256 + n], W1[(k + 1) * 256 + n]);
            *(uint32_t*)(gW1t + c * CHUNK_BYTES + (n * SC + kk) * 2) = *(uint32_t*)&h;
        } else {                                        // W2t chunked
            const int k = (t - 192) * 2;
            const int c = k >> 7, kk = k & 127;
            __half2 h = __floats2half2_rn(W2[k * 256 + n], W2[(k + 1) * 256 + n]);
            *(uint32_t*)(gW2t + c * CHUNK_BYTES + (n * SC + kk) * 2) = *(uint32_t*)&h;
        }
    }
    if (idx < 256) {
        gParams[PB0 + idx] = b0[idx];
        gParams[PB1 + idx] = b1[idx];
        gParams[PB2 + idx] = b2[idx];
        gParams[PWC + idx] = Wc[(idx >> 6) * 256 + idx];
        gParams[PWOCC + idx] = Wocc[idx];
    } else if (idx < 260) {
        gParams[PBC + idx - 256] = bc[idx - 256];
    } else if (idx == 260) {
        gParams[PBOCC] = bocc[0];
    }
}

// ---------------- warp GEMM: 32x64 tile, f16-acc, promote every K=32 ----------------
template <int KSTEPS, bool ZERO>
__device__ __forceinline__ void run_gemm(float (&acc)[2][8][4],
                                         uint32_t aAddr, uint32_t aOff16,
                                         uint32_t bAddr, uint32_t bJ)
{
    static_assert(KSTEPS % 2 == 0, "KSTEPS must be even");
    if (ZERO) {
#pragma unroll
        for (int rt = 0; rt < 2; ++rt)
#pragma unroll
            for (int ct = 0; ct < 8; ++ct)
#pragma unroll
                for (int q = 0; q < 4; ++q) acc[rt][ct][q] = 0.f;
    }
#pragma unroll 2
    for (int kp = 0; kp < KSTEPS / 2; ++kp) {
        uint32_t a00[4], a01[4], a10[4], a11[4];
        ldmx4(a00, aAddr);                 // rows 0-15,  k0
        ldmx4(a10, aAddr + aOff16);        // rows 16-31, k0
        ldmx4(a01, aAddr + 32);            // rows 0-15,  k1
        ldmx4(a11, aAddr + aOff16 + 32);   // rows 16-31, k1
        aAddr += 64;
#pragma unroll
        for (int j = 0; j < 4; ++j) {
            uint32_t b0[4], b1[4];
            ldmx4(b0, bAddr + j * bJ);         // k0: cols 2j(0,1) / 2j+1(2,3)
            ldmx4(b1, bAddr + j * bJ + 32);    // k1
            mma2_promote(acc[0][2 * j],     a00, a01, b0[0], b0[1], b1[0], b1[1]);
            mma2_promote(acc[0][2 * j + 1], a00, a01, b0[2], b0[3], b1[2], b1[3]);
            mma2_promote(acc[1][2 * j],     a10, a11, b0[0], b0[1], b1[0], b1[1]);
            mma2_promote(acc[1][2 * j + 1], a10, a11, b0[2], b0[3], b1[2], b1[3]);
        }
        bAddr += 64;
    }
}

// ---------------- main kernel ----------------
__global__ __launch_bounds__(THREADS, 1)
void mlp3d_mma(const float* __restrict__ coords,
               float* __restrict__ out_occ, float* __restrict__ out_cls, int npts)
{
    extern __shared__ unsigned char sm[];
    const uint32_t sb = smem_u32(sm);
    float* sPar = (float*)(sm + OFF_PAR);
    float* sOcc = (float*)(sm + OFF_OCC);

    const int tid = threadIdx.x;
    const int lane = tid & 31, wid = tid >> 5;
    const int wr = wid >> 2, wc = wid & 3;        // 4 row groups x 4 col groups
    const int gid = lane >> 2, tid4 = lane & 3;
    const int nbase = blockIdx.x * 128;

    // group A: W0t -> WB0 ; group B: W1bd -> WB1
    for (int i = tid * 16; i < SMALL_BYTES; i += THREADS * 16)
        cp16(sb + OFF_WB0 + i, gW0t + i);
    CP_COMMIT();
    for (int i = tid * 16; i < SMALL_BYTES; i += THREADS * 16)
        cp16(sb + OFF_WB1 + i, gW1bd + i);
    CP_COMMIT();

    // embed rows 0..127 (threads 0-127, E inside X region) || params (128-255)
    if (tid < 128) {
        const int n = nbase + tid;
        float c3[3] = {0.f, 0.f, 0.f};
        if (n < npts) {
            c3[0] = coords[n * 3 + 0];
            c3[1] = coords[n * 3 + 1];
            c3[2] = coords[n * 3 + 2];
        }
        __half* e = (__half*)(sm + OFF_X) + tid * SE;
        e[63] = __float2half_rn(0.f);
#pragma unroll
        for (int d = 0; d < 3; ++d) {
            e[d] = __float2half_rn(c3[d]);
            float s, co;
            sincosf(c3[d], &s, &co);
#pragma unroll
            for (int f = 0; f < 10; ++f) {
                e[3 + f * 6 + d] = __float2half_rn(s);
                e[6 + f * 6 + d] = __float2half_rn(co);
                const float s2 = 2.f * s * co;
                const float c2 = fmaf(-2.f * s, s, 1.f);
                s = s2; co = c2;
            }
        }
    } else if (tid < 256) {
        for (int i = tid - 128; i < NPAR; i += 128) sPar[i] = gParams[i];
    }
    CP_WAIT(1);          // A visible (B may pend)
    __syncthreads();

    // ldmatrix lane address components
    const int aRow = (lane & 7) + ((lane >> 3) & 1) * 8;
    const int aK   = ((lane >> 4) & 1) * 8;
    const int bRow = (lane & 7) + ((lane >> 4) & 1) * 8;
    const int bK   = ((lane >> 3) & 1) * 8;
    const uint32_t bW0 = sb + OFF_WB0 + ((wc * 64 + bRow) * SW + bK) * 2;
    const uint32_t bBD = sb + OFF_WB1 + ((wc * 64 + bRow) * SW + bK) * 2;
    const uint32_t bC0 = sb + OFF_WB0 + ((wc * 64 + bRow) * SC + bK) * 2;
    const uint32_t bC1 = sb + OFF_WB1 + ((wc * 64 + bRow) * SC + bK) * 2;
    const uint32_t bJs = 16 * SW * 2, bJc = 16 * SC * 2;

    const uint32_t aE = sb + OFF_X + ((wr * 32 + aRow) * SE + aK) * 2;
    const uint32_t aX = sb + OFF_X + ((wr * 32 + aRow) * SA + aK) * 2;
    const uint32_t aO16e = 16 * SE * 2, aO16 = 16 * SA * 2;

    float acc[2][8][4];

    // ================= P0: X = E @ W0t^T + b0 =================
    run_gemm<4, true>(acc, aE, aO16e, bW0, bJs);
    __syncthreads();                             // all E reads done; WB0 dead
    // group C: W1t.c0 -> WB0
    for (int i = tid * 16; i < CHUNK_BYTES; i += THREADS * 16)
        cp16(sb + OFF_WB0 + i, gW1t + i);
    CP_COMMIT();
    {
        unsigned char* xB = sm + OFF_X;
#pragma unroll
        for (int rt = 0; rt < 2; ++rt) {
            const int r0 = wr * 32 + rt * 16 + gid;
#pragma unroll
            for (int ct = 0; ct < 8; ++ct) {
                const int c = wc * 64 + ct * 8 + tid4 * 2;
                const float bv0 = sPar[PB0 + c], bv1 = sPar[PB0 + c + 1];
                __half2 h0 = __floats2half2_rn(acc[rt][ct][0] + bv0, acc[rt][ct][1] + bv1);
                __half2 h1 = __floats2half2_rn(acc[rt][ct][2] + bv0, acc[rt][ct][3] + bv1);
                *(uint32_t*)(xB + (r0 * SA + c) * 2) = *(uint32_t*)&h0;
                *(uint32_t*)(xB + ((r0 + 8) * SA + c) * 2) = *(uint32_t*)&h1;
            }
        }
    }
    CP_WAIT(1);          // B visible (C pends)
    __syncthreads();     // X ready

    // ================= P1: part branches + class heads =================
    run_gemm<4, true>(acc, aX + wc * 64 * 2, aO16, bBD, bJs);
    {
        const int p = wc;
#pragma unroll
        for (int rt = 0; rt < 2; ++rt) {
            float s0 = 0.f, s1 = 0.f;
#pragma unroll
            for (int ct = 0; ct < 8; ++ct) {
                const int c = wc * 64 + ct * 8 + tid4 * 2;
                const float b0v = sPar[PB1 + c], b1v = sPar[PB1 + c + 1];
                const float w0v = sPar[PWC + c], w1v = sPar[PWC + c + 1];
                s0 = fmaf(fmaxf(acc[rt][ct][0] + b0v, 0.f), w0v, s0);
                s0 = fmaf(fmaxf(acc[rt][ct][1] + b1v, 0.f), w1v, s0);
                s1 = fmaf(fmaxf(acc[rt][ct][2] + b0v, 0.f), w0v, s1);
                s1 = fmaf(fmaxf(acc[rt][ct][3] + b1v, 0.f), w1v, s1);
            }
            s0 += __shfl_xor_sync(0xffffffffu, s0, 1);
            s0 += __shfl_xor_sync(0xffffffffu, s0, 2);
            s1 += __shfl_xor_sync(0xffffffffu, s1, 1);
            s1 += __shfl_xor_sync(0xffffffffu, s1, 2);
            if (tid4 == 0) {
                const float bcp = sPar[PBC + p];
                int n = nbase + wr * 32 + rt * 16 + gid;
                if (n < npts) out_cls[n * 4 + p] = s0 + bcp;
                n += 8;
                if (n < npts) out_cls[n * 4 + p] = s1 + bcp;
            }
        }
    }
    __syncthreads();     // WB1 (W1bd) dead
    // group D: W1t.c1 -> WB1
    for (int i = tid * 16; i < CHUNK_BYTES; i += THREADS * 16)
        cp16(sb + OFF_WB1 + i, gW1t + CHUNK_BYTES + i);
    CP_COMMIT();
    CP_WAIT(1);          // C visible (D pends)
    __syncthreads();

    // ================= P2: A1 = relu(X @ W1t + b1), K-chunked =================
    run_gemm<8, true>(acc, aX, aO16, bC0, bJc);
    __syncthreads();     // WB0 dead
    // group E: W2t.c0 -> WB0
    for (int i = tid * 16; i < CHUNK_BYTES; i += THREADS * 16)
        cp16(sb + OFF_WB0 + i, gW2t + i);
    CP_COMMIT();
    CP_WAIT(1);          // D visible (E pends)
    __syncthreads();
    run_gemm<8, false>(acc, aX + 256, aO16, bC1, bJc);
    __syncthreads();     // WB1 dead; all X reads done
    // group F: W2t.c1 -> WB1
    for (int i = tid * 16; i < CHUNK_BYTES; i += THREADS * 16)
        cp16(sb + OFF_WB1 + i, gW2t + CHUNK_BYTES + i);
    CP_COMMIT();
    {   // epilogue: A1 -> X in place
        unsigned char* xB = sm + OFF_X;
#pragma unroll
        for (int rt = 0; rt < 2; ++rt) {
            const int r0 = wr * 32 + rt * 16 + gid;
#pragma unroll
            for (int ct = 0; ct < 8; ++ct) {
                const int c = wc * 64 + ct * 8 + tid4 * 2;
                const float bv0 = sPar[PB1 + c], bv1 = sPar[PB1 + c + 1];
                __half2 h0 = __floats2half2_rn(fmaxf(acc[rt][ct][0] + bv0, 0.f),
                                               fmaxf(acc[rt][ct][1] + bv1, 0.f));
                __half2 h1 = __floats2half2_rn(fmaxf(acc[rt][ct][2] + bv0, 0.f),
                                               fmaxf(acc[rt][ct][3] + bv1, 0.f));
                *(uint32_t*)(xB + (r0 * SA + c) * 2) = *(uint32_t*)&h0;
                *(uint32_t*)(xB + ((r0 + 8) * SA + c) * 2) = *(uint32_t*)&h1;
            }
        }
    }
    CP_WAIT(1);          // E visible (F pends)
    __syncthreads();     // A1 ready

    // ================= P3: occ, K-chunked =================
    run_gemm<8, true>(acc, aX, aO16, bC0, bJc);
    CP_WAIT(0);          // F visible
    __syncthreads();
    run_gemm<8, false>(acc, aX + 256, aO16, bC1, bJc);
#pragma unroll
    for (int rt = 0; rt < 2; ++rt) {
        float s0 = 0.f, s1 = 0.f;
#pragma unroll
        for (int ct = 0; ct < 8; ++ct) {
            const int c = wc * 64 + ct * 8 + tid4 * 2;
            const float b0v = sPar[PB2 + c], b1v = sPar[PB2 + c + 1];
            const float w0v = sPar[PWOCC + c], w1v = sPar[PWOCC + c + 1];
            s0 = fmaf(fmaxf(acc[rt][ct][0] + b0v, 0.f), w0v, s0);
            s0 = fmaf(fmaxf(acc[rt][ct][1] + b1v, 0.f), w1v, s0);
            s1 = fmaf(fmaxf(acc[rt][ct][2] + b0v, 0.f), w0v, s1);
            s1 = fmaf(fmaxf(acc[rt][ct][3] + b1v, 0.f), w1v, s1);
        }
        s0 += __shfl_xor_sync(0xffffffffu, s0, 1);
        s0 += __shfl_xor_sync(0xffffffffu, s0, 2);
        s1 += __shfl_xor_sync(0xffffffffu, s1, 1);
        s1 += __shfl_xor_sync(0xffffffffu, s1, 2);
        if (tid4 == 0) {
            const int r = wr * 32 + rt * 16 + gid;
            sOcc[r * 4 + wc] = s0;
            sOcc[(r + 8) * 4 + wc] = s1;
        }
    }
    __syncthreads();
    if (tid < 128) {
        const float v = sOcc[tid * 4] + sOcc[tid * 4 + 1] + sOcc[tid * 4 + 2] +
                        sOcc[tid * 4 + 3] + sPar[PBOCC];
        const int n = nbase + tid;
        if (n < npts) out_occ[n] = v;
    }
}

// ---------------- launch ----------------
extern "C" void kernel_launch(void* const* d_in, const int* in_sizes, int n_in,
                              void* d_out, int out_size) {
    const float* coords = (const float*)d_in[0];
    const float* W0   = (const float*)d_in[1];
    const float* b0   = (const float*)d_in[2];
    const float* W1   = (const float*)d_in[3];
    const float* b1   = (const float*)d_in[4];
    const float* W2   = (const float*)d_in[5];
    const float* b2   = (const float*)d_in[6];
    const float* Wocc = (const float*)d_in[7];
    const float* bocc = (const float*)d_in[8];
    const float* Wc   = (const float*)d_in[9];
    const float* bc   = (const float*)d_in[10];

    const int npts = in_sizes[0] / 3;
    float* out_occ = (float*)d_out;
    float* out_cls = (float*)d_out + npts;

    prep_kernel<<<320, 256>>>(W0, b0, W1, b1, W2, b2, Wocc, bocc, Wc, bc);

    cudaFuncSetAttribute(mlp3d_mma, cudaFuncAttributeMaxDynamicSharedMemorySize, SMEM_BYTES);
    const int blocks = (npts + 127) / 128;
    mlp3d_mma<<<blocks, THREADS, SMEM_BYTES>>>(coords, out_occ, out_cls, npts);
}

// round 11
// speedup vs baseline: 1.2371x; 1.2371x over previous
#include <cuda_runtime.h>
#include <cuda_fp16.h>
#include <cstdint>

// MLP3D_final — mma.sync HMMA (f16 in / f32 acc), 64-point blocks, 256 threads,
// 2 blocks/SM co-residency (the second block's instruction stream fills the
// tensor pipe during the first block's epilogues/staging).
// Big weights staged as four K=64 chunks through double-buffered WB0/WB1.
//
// Per block (8 warps = 2 row x 4 col over 64x256, warp tile 32x64):
//   A:W0t->WB0, B:W1bd->WB1 || embed->E (inside X) || params
//   P0 : X = E @ W0t^T + b0           ; then C: W1t.c0->WB0
//   P1 : part cls heads (X @ W1bd)    ; then D: W1t.c1->WB1
//   P2 : A1 = relu(X @ W1t + b1), 4 K-chunks alternating WB0/WB1,
//        staging W1t.c2, W1t.c3, W2t.c0, W2t.c1 behind the gemms
//   P3 : occ = relu(A1 @ W2t + b2) . Wocc, 4 K-chunks (stage W2t.c2, c3)

#define THREADS 256

// strides in f16 elements
#define SA 264   // activation rows (256 + 8 pad)
#define SE 72    // embedding rows (64 + 8 pad)
#define SW 72    // weight chunk images (k=64 + 8 pad)

#define WB_BYTES 36864               // 256 * SW * 2

// smem byte offsets
#define OFF_WB0 0
#define OFF_WB1 36864
#define OFF_X   73728                // 64 * SA * 2 = 33792
#define OFF_PAR 107520
#define OFF_OCC 112704               // 64*4*4 = 1024
#define SMEM_BYTES 113728

// param vector layout (floats)
#define PB0 0
#define PB1 256
#define PB2 512
#define PWC 768
#define PWOCC 1024
#define PBC 1280
#define PBOCC 1284
#define NPAR 1285

__device__ __align__(16) unsigned char gW0t[WB_BYTES];
__device__ __align__(16) unsigned char gW1bd[WB_BYTES];
__device__ __align__(16) unsigned char gW1t[4 * WB_BYTES];   // 4 k-chunks
__device__ __align__(16) unsigned char gW2t[4 * WB_BYTES];   // 4 k-chunks
__device__ float gParams[NPAR];

// ---------------- PTX helpers ----------------
__device__ __forceinline__ uint32_t smem_u32(const void* p) {
    uint32_t a;
    asm("{ .reg .u64 t; cvta.to.shared.u64 t, %1; cvt.u32.u64 %0, t; }" : "=r"(a) : "l"(p));
    return a;
}
__device__ __forceinline__ void ldmx4(uint32_t* r, uint32_t a) {
    asm volatile("ldmatrix.sync.aligned.m8n8.x4.shared.b16 {%0,%1,%2,%3}, [%4];"
                 : "=r"(r[0]), "=r"(r[1]), "=r"(r[2]), "=r"(r[3]) : "r"(a));
}
__device__ __forceinline__ void mma16816(float* d, const uint32_t* a, uint32_t b0, uint32_t b1) {
    asm volatile(
        "mma.sync.aligned.m16n8k16.row.col.f32.f16.f16.f32 "
        "{%0,%1,%2,%3}, {%4,%5,%6,%7}, {%8,%9}, {%0,%1,%2,%3};"
        : "+f"(d[0]), "+f"(d[1]), "+f"(d[2]), "+f"(d[3])
        : "r"(a[0]), "r"(a[1]), "r"(a[2]), "r"(a[3]), "r"(b0), "r"(b1));
}
__device__ __forceinline__ void cp16(uint32_t dst, const void* src) {
    asm volatile("cp.async.cg.shared.global [%0], [%1], 16;" :: "r"(dst), "l"(src));
}
#define CP_COMMIT() asm volatile("cp.async.commit_group;" ::: "memory")
#define CP_WAIT(n)  asm volatile("cp.async.wait_group %0;" :: "n"(n) : "memory")

// ---------------- prep kernel ----------------
__global__ void prep_kernel(
    const float* __restrict__ W0, const float* __restrict__ b0,
    const float* __restrict__ W1, const float* __restrict__ b1,
    const float* __restrict__ W2, const float* __restrict__ b2,
    const float* __restrict__ Wocc, const float* __restrict__ bocc,
    const float* __restrict__ Wc, const float* __restrict__ bc)
{
    const int idx = blockIdx.x * blockDim.x + threadIdx.x;
    const int stride = gridDim.x * blockDim.x;
    for (int i = idx; i < 256 * 320; i += stride) {
        const int n = i & 255;
        const int t = i >> 8;
        if (t < 32) {                                   // W0t [n][k<64]
            const int k = t * 2;
            const float v0 = (k < 63) ? W0[k * 256 + n] : 0.f;
            const float v1 = (k + 1 < 63) ? W0[(k + 1) * 256 + n] : 0.f;
            __half2 h = __floats2half2_rn(v0, v1);
            *(uint32_t*)(gW0t + (n * SW + k) * 2) = *(uint32_t*)&h;
        } else if (t < 64) {                            // W1bdT diag blocks
            const int k = (t - 32) * 2;
            const int base = (n >> 6) * 64;
            __half2 h = __floats2half2_rn(W1[(base + k) * 256 + n],
                                          W1[(base + k + 1) * 256 + n]);
            *(uint32_t*)(gW1bd + (n * SW + k) * 2) = *(uint32_t*)&h;
        } else if (t < 192) {                           // W1t, k=64 chunks
            const int k = (t - 64) * 2;
            const int c = k >> 6, kk = k & 63;
            __half2 h = __floats2half2_rn(W1[k * 256 + n], W1[(k + 1) * 256 + n]);
            *(uint32_t*)(gW1t + c * WB_BYTES + (n * SW + kk) * 2) = *(uint32_t*)&h;
        } else {                                        // W2t, k=64 chunks
            const int k = (t - 192) * 2;
            const int c = k >> 6, kk = k & 63;
            __half2 h = __floats2half2_rn(W2[k * 256 + n], W2[(k + 1) * 256 + n]);
            *(uint32_t*)(gW2t + c * WB_BYTES + (n * SW + kk) * 2) = *(uint32_t*)&h;
        }
    }
    if (idx < 256) {
        gParams[PB0 + idx] = b0[idx];
        gParams[PB1 + idx] = b1[idx];
        gParams[PB2 + idx] = b2[idx];
        gParams[PWC + idx] = Wc[(idx >> 6) * 256 + idx];
        gParams[PWOCC + idx] = Wocc[idx];
    } else if (idx < 260) {
        gParams[PBC + idx - 256] = bc[idx - 256];
    } else if (idx == 260) {
        gParams[PBOCC] = bocc[0];
    }
}

// ---------------- warp GEMM: 32x64 tile, K=64 (4 ksteps) ----------------
template <bool ZERO>
__device__ __forceinline__ void run_gemm64(float (&acc)[2][8][4],
                                           uint32_t aAddr, uint32_t aOff16,
                                           uint32_t bAddr)
{
    if (ZERO) {
#pragma unroll
        for (int rt = 0; rt < 2; ++rt)
#pragma unroll
            for (int ct = 0; ct < 8; ++ct)
#pragma unroll
                for (int q = 0; q < 4; ++q) acc[rt][ct][q] = 0.f;
    }
#pragma unroll
    for (int ks = 0; ks < 4; ++ks) {
        uint32_t a0[4], a1[4], b[4][4];
        ldmx4(a0, aAddr);
        ldmx4(a1, aAddr + aOff16);
#pragma unroll
        for (int j = 0; j < 4; ++j) ldmx4(b[j], bAddr + j * (16 * SW * 2));
        aAddr += 32;
        bAddr += 32;
#pragma unroll
        for (int j = 0; j < 4; ++j) {
            mma16816(acc[0][2 * j],     a0, b[j][0], b[j][1]);
            mma16816(acc[0][2 * j + 1], a0, b[j][2], b[j][3]);
            mma16816(acc[1][2 * j],     a1, b[j][0], b[j][1]);
            mma16816(acc[1][2 * j + 1], a1, b[j][2], b[j][3]);
        }
    }
}

// ---------------- main kernel ----------------
__global__ __launch_bounds__(THREADS, 2)
void mlp3d_mma(const float* __restrict__ coords,
               float* __restrict__ out_occ, float* __restrict__ out_cls, int npts)
{
    extern __shared__ unsigned char sm[];
    const uint32_t sb = smem_u32(sm);
    float* sPar = (float*)(sm + OFF_PAR);
    float* sOcc = (float*)(sm + OFF_OCC);

    const int tid = threadIdx.x;
    const int lane = tid & 31, wid = tid >> 5;
    const int wr = wid >> 2, wc = wid & 3;        // 2 row groups x 4 col groups
    const int gid = lane >> 2, tid4 = lane & 3;
    const int nbase = blockIdx.x * 64;

    // group A: W0t -> WB0 ; group B: W1bd -> WB1
    for (int i = tid * 16; i < WB_BYTES; i += THREADS * 16)
        cp16(sb + OFF_WB0 + i, gW0t + i);
    CP_COMMIT();
    for (int i = tid * 16; i < WB_BYTES; i += THREADS * 16)
        cp16(sb + OFF_WB1 + i, gW1bd + i);
    CP_COMMIT();

    // embed rows 0..63 (threads 0-63, E inside X region) || params (64-191)
    if (tid < 64) {
        const int n = nbase + tid;
        float c3[3] = {0.f, 0.f, 0.f};
        if (n < npts) {
            c3[0] = coords[n * 3 + 0];
            c3[1] = coords[n * 3 + 1];
            c3[2] = coords[n * 3 + 2];
        }
        __half* e = (__half*)(sm + OFF_X) + tid * SE;
        e[63] = __float2half_rn(0.f);
#pragma unroll
        for (int d = 0; d < 3; ++d) {
            e[d] = __float2half_rn(c3[d]);
            float s, co;
            sincosf(c3[d], &s, &co);
#pragma unroll
            for (int f = 0; f < 10; ++f) {
                e[3 + f * 6 + d] = __float2half_rn(s);
                e[6 + f * 6 + d] = __float2half_rn(co);
                const float s2 = 2.f * s * co;
                const float c2 = fmaf(-2.f * s, s, 1.f);
                s = s2; co = c2;
            }
        }
    } else if (tid < 192) {
        for (int i = tid - 64; i < NPAR; i += 128) sPar[i] = gParams[i];
    }
    CP_WAIT(1);          // A visible (B may pend)
    __syncthreads();

    // ldmatrix lane address components
    const int aRow = (lane & 7) + ((lane >> 3) & 1) * 8;
    const int aK   = ((lane >> 4) & 1) * 8;
    const int bRow = (lane & 7) + ((lane >> 4) & 1) * 8;
    const int bK   = ((lane >> 3) & 1) * 8;
    const uint32_t bB0 = sb + OFF_WB0 + ((wc * 64 + bRow) * SW + bK) * 2;
    const uint32_t bB1 = sb + OFF_WB1 + ((wc * 64 + bRow) * SW + bK) * 2;

    const uint32_t aE = sb + OFF_X + ((wr * 32 + aRow) * SE + aK) * 2;
    const uint32_t aX = sb + OFF_X + ((wr * 32 + aRow) * SA + aK) * 2;
    const uint32_t aO16e = 16 * SE * 2, aO16 = 16 * SA * 2;

    float acc[2][8][4];

    // ================= P0: X = E @ W0t^T + b0 =================
    run_gemm64<true>(acc, aE, aO16e, bB0);
    __syncthreads();                             // E reads done; WB0 dead
    // group C: W1t.c0 -> WB0
    for (int i = tid * 16; i < WB_BYTES; i += THREADS * 16)
        cp16(sb + OFF_WB0 + i, gW1t + i);
    CP_COMMIT();
    {
        unsigned char* xB = sm + OFF_X;
#pragma unroll
        for (int rt = 0; rt < 2; ++rt) {
            const int r0 = wr * 32 + rt * 16 + gid;
#pragma unroll
            for (int ct = 0; ct < 8; ++ct) {
                const int c = wc * 64 + ct * 8 + tid4 * 2;
                const float bv0 = sPar[PB0 + c], bv1 = sPar[PB0 + c + 1];
                __half2 h0 = __floats2half2_rn(acc[rt][ct][0] + bv0, acc[rt][ct][1] + bv1);
                __half2 h1 = __floats2half2_rn(acc[rt][ct][2] + bv0, acc[rt][ct][3] + bv1);
                *(uint32_t*)(xB + (r0 * SA + c) * 2) = *(uint32_t*)&h0;
                *(uint32_t*)(xB + ((r0 + 8) * SA + c) * 2) = *(uint32_t*)&h1;
            }
        }
    }
    CP_WAIT(1);          // B visible (C pends)
    __syncthreads();     // X ready

    // ================= P1: part branches + class heads =================
    run_gemm64<true>(acc, aX + wc * 64 * 2, aO16, bB1);
    {
        const int p = wc;
#pragma unroll
        for (int rt = 0; rt < 2; ++rt) {
            float s0 = 0.f, s1 = 0.f;
#pragma unroll
            for (int ct = 0; ct < 8; ++ct) {
                const int c = wc * 64 + ct * 8 + tid4 * 2;
                const float b0v = sPar[PB1 + c], b1v = sPar[PB1 + c + 1];
                const float w0v = sPar[PWC + c], w1v = sPar[PWC + c + 1];
                s0 = fmaf(fmaxf(acc[rt][ct][0] + b0v, 0.f), w0v, s0);
                s0 = fmaf(fmaxf(acc[rt][ct][1] + b1v, 0.f), w1v, s0);
                s1 = fmaf(fmaxf(acc[rt][ct][2] + b0v, 0.f), w0v, s1);
                s1 = fmaf(fmaxf(acc[rt][ct][3] + b1v, 0.f), w1v, s1);
            }
            s0 += __shfl_xor_sync(0xffffffffu, s0, 1);
            s0 += __shfl_xor_sync(0xffffffffu, s0, 2);
            s1 += __shfl_xor_sync(0xffffffffu, s1, 1);
            s1 += __shfl_xor_sync(0xffffffffu, s1, 2);
            if (tid4 == 0) {
                const float bcp = sPar[PBC + p];
                int n = nbase + wr * 32 + rt * 16 + gid;
                if (n < npts) out_cls[n * 4 + p] = s0 + bcp;
                n += 8;
                if (n < npts) out_cls[n * 4 + p] = s1 + bcp;
            }
        }
    }
    __syncthreads();     // WB1 (W1bd) dead
    // group D: W1t.c1 -> WB1
    for (int i = tid * 16; i < WB_BYTES; i += THREADS * 16)
        cp16(sb + OFF_WB1 + i, gW1t + WB_BYTES + i);
    CP_COMMIT();
    CP_WAIT(1);          // C visible (D pends)
    __syncthreads();

    // ================= P2: A1 = relu(X @ W1t + b1), 4 K-chunks =================
    // chunk 0 (WB0), then stage W1t.c2 -> WB0
    run_gemm64<true>(acc, aX + 0 * 128, aO16, bB0);
    __syncthreads();
    for (int i = tid * 16; i < WB_BYTES; i += THREADS * 16)
        cp16(sb + OFF_WB0 + i, gW1t + 2 * WB_BYTES + i);
    CP_COMMIT();
    CP_WAIT(1);          // D visible
    __syncthreads();
    // chunk 1 (WB1), then stage W1t.c3 -> WB1
    run_gemm64<false>(acc, aX + 1 * 128, aO16, bB1);
    __syncthreads();
    for (int i = tid * 16; i < WB_BYTES; i += THREADS * 16)
        cp16(sb + OFF_WB1 + i, gW1t + 3 * WB_BYTES + i);
    CP_COMMIT();
    CP_WAIT(1);          // W1t.c2 visible
    __syncthreads();
    // chunk 2 (WB0), then stage W2t.c0 -> WB0
    run_gemm64<false>(acc, aX + 2 * 128, aO16, bB0);
    __syncthreads();
    for (int i = tid * 16; i < WB_BYTES; i += THREADS * 16)
        cp16(sb + OFF_WB0 + i, gW2t + i);
    CP_COMMIT();
    CP_WAIT(1);          // W1t.c3 visible
    __syncthreads();
    // chunk 3 (WB1), then stage W2t.c1 -> WB1
    run_gemm64<false>(acc, aX + 3 * 128, aO16, bB1);
    __syncthreads();     // all X reads done
    for (int i = tid * 16; i < WB_BYTES; i += THREADS * 16)
        cp16(sb + OFF_WB1 + i, gW2t + WB_BYTES + i);
    CP_COMMIT();
    {   // epilogue: A1 -> X in place
        unsigned char* xB = sm + OFF_X;
#pragma unroll
        for (int rt = 0; rt < 2; ++rt) {
            const int r0 = wr * 32 + rt * 16 + gid;
#pragma unroll
            for (int ct = 0; ct < 8; ++ct) {
                const int c = wc * 64 + ct * 8 + tid4 * 2;
                const float bv0 = sPar[PB1 + c], bv1 = sPar[PB1 + c + 1];
                __half2 h0 = __floats2half2_rn(fmaxf(acc[rt][ct][0] + bv0, 0.f),
                                               fmaxf(acc[rt][ct][1] + bv1, 0.f));
                __half2 h1 = __floats2half2_rn(fmaxf(acc[rt][ct][2] + bv0, 0.f),
                                               fmaxf(acc[rt][ct][3] + bv1, 0.f));
                *(uint32_t*)(xB + (r0 * SA + c) * 2) = *(uint32_t*)&h0;
                *(uint32_t*)(xB + ((r0 + 8) * SA + c) * 2) = *(uint32_t*)&h1;
            }
        }
    }
    CP_WAIT(1);          // W2t.c0 visible
    __syncthreads();     // A1 ready

    // ================= P3: occ, 4 K-chunks =================
    run_gemm64<true>(acc, aX + 0 * 128, aO16, bB0);
    __syncthreads();
    for (int i = tid * 16; i < WB_BYTES; i += THREADS * 16)
        cp16(sb + OFF_WB0 + i, gW2t + 2 * WB_BYTES + i);
    CP_COMMIT();
    CP_WAIT(1);          // W2t.c1 visible
    __syncthreads();
    run_gemm64<false>(acc, aX + 1 * 128, aO16, bB1);
    __syncthreads();
    for (int i = tid * 16; i < WB_BYTES; i += THREADS * 16)
        cp16(sb + OFF_WB1 + i, gW2t + 3 * WB_BYTES + i);
    CP_COMMIT();
    CP_WAIT(1);          // W2t.c2 visible
    __syncthreads();
    run_gemm64<false>(acc, aX + 2 * 128, aO16, bB0);
    CP_WAIT(0);          // W2t.c3 visible
    __syncthreads();
    run_gemm64<false>(acc, aX + 3 * 128, aO16, bB1);
#pragma unroll
    for (int rt = 0; rt < 2; ++rt) {
        float s0 = 0.f, s1 = 0.f;
#pragma unroll
        for (int ct = 0; ct < 8; ++ct) {
            const int c = wc * 64 + ct * 8 + tid4 * 2;
            const float b0v = sPar[PB2 + c], b1v = sPar[PB2 + c + 1];
            const float w0v = sPar[PWOCC + c], w1v = sPar[PWOCC + c + 1];
            s0 = fmaf(fmaxf(acc[rt][ct][0] + b0v, 0.f), w0v, s0);
            s0 = fmaf(fmaxf(acc[rt][ct][1] + b1v, 0.f), w1v, s0);
            s1 = fmaf(fmaxf(acc[rt][ct][2] + b0v, 0.f), w0v, s1);
            s1 = fmaf(fmaxf(acc[rt][ct][3] + b1v, 0.f), w1v, s1);
        }
        s0 += __shfl_xor_sync(0xffffffffu, s0, 1);
        s0 += __shfl_xor_sync(0xffffffffu, s0, 2);
        s1 += __shfl_xor_sync(0xffffffffu, s1, 1);
        s1 += __shfl_xor_sync(0xffffffffu, s1, 2);
        if (tid4 == 0) {
            const int r = wr * 32 + rt * 16 + gid;
            sOcc[r * 4 + wc] = s0;
            sOcc[(r + 8) * 4 + wc] = s1;
        }
    }
    __syncthreads();
    if (tid < 64) {
        const float v = sOcc[tid * 4] + sOcc[tid * 4 + 1] + sOcc[tid * 4 + 2] +
                        sOcc[tid * 4 + 3] + sPar[PBOCC];
        const int n = nbase + tid;
        if (n < npts) out_occ[n] = v;
    }
}

// ---------------- launch ----------------
extern "C" void kernel_launch(void* const* d_in, const int* in_sizes, int n_in,
                              void* d_out, int out_size) {
    const float* coords = (const float*)d_in[0];
    const float* W0   = (const float*)d_in[1];
    const float* b0   = (const float*)d_in[2];
    const float* W1   = (const float*)d_in[3];
    const float* b1   = (const float*)d_in[4];
    const float* W2   = (const float*)d_in[5];
    const float* b2   = (const float*)d_in[6];
    const float* Wocc = (const float*)d_in[7];
    const float* bocc = (const float*)d_in[8];
    const float* Wc   = (const float*)d_in[9];
    const float* bc   = (const float*)d_in[10];

    const int npts = in_sizes[0] / 3;
    float* out_occ = (float*)d_out;
    float* out_cls = (float*)d_out + npts;

    prep_kernel<<<320, 256>>>(W0, b0, W1, b1, W2, b2, Wocc, bocc, Wc, bc);

    cudaFuncSetAttribute(mlp3d_mma, cudaFuncAttributeMaxDynamicSharedMemorySize, SMEM_BYTES);
    const int blocks = (npts + 63) / 64;
    mlp3d_mma<<<blocks, THREADS, SMEM_BYTES>>>(coords, out_occ, out_cls, npts);
}

// round 13
// speedup vs baseline: 1.2392x; 1.0017x over previous
#include <cuda_runtime.h>
#include <cuda_fp16.h>
#include <cstdint>

// MLP3D_final — mma.sync HMMA (f16 in / f32 acc), 64x64 warp tiles to cut
// ldmatrix bytes/MMA from 192 to 128 (smem crossbar was co-binding with the
// tensor pipe at 32x64). 128-pt blocks, 256 threads = 8 warps (2 row x 4 col),
// acc[4][8][4] per warp; K-chunked double-buffered weight staging (as R5).
//
// Phases:
//   A:W0t->WB0, B:W1bd->WB1 || embed->E (inside X) || params
//   P0 : X = E @ W0t^T + b0            ; then C: W1t.c0->WB0
//   P1 : part cls heads (X @ W1bd)     ; then D: W1t.c1->WB1
//   P2 : A1 = relu(X @ W1t + b1), 2 K-chunks; stage E,F (W2t.c0/c1) behind
//   P3 : occ = relu(A1 @ W2t + b2) . Wocc, 2 K-chunks

#define THREADS 256

// strides in f16 elements
#define SA 264   // activation rows (256 + 8 pad)
#define SE 72    // embedding rows (64 + 8 pad)
#define SW 72    // small weight images (k=64 + 8 pad)
#define SC 136   // big-weight chunk images (k=128 + 8 pad)

#define CHUNK_BYTES (256 * SC * 2)   // 69632
#define SMALL_BYTES (256 * SW * 2)   // 36864

// smem byte offsets
#define OFF_WB0 0
#define OFF_WB1 69632
#define OFF_X   139264               // 128 * SA * 2 = 67584
#define OFF_PAR 206848
#define OFF_OCC 212032               // 128*4*4 = 2048
#define SMEM_BYTES 214080

// param vector layout (floats)
#define PB0 0
#define PB1 256
#define PB2 512
#define PWC 768
#define PWOCC 1024
#define PBC 1280
#define PBOCC 1284
#define NPAR 1285

__device__ __align__(16) unsigned char gW0t[SMALL_BYTES];
__device__ __align__(16) unsigned char gW1bd[SMALL_BYTES];
__device__ __align__(16) unsigned char gW1t[2 * CHUNK_BYTES];
__device__ __align__(16) unsigned char gW2t[2 * CHUNK_BYTES];
__device__ float gParams[NPAR];

// ---------------- PTX helpers ----------------
__device__ __forceinline__ uint32_t smem_u32(const void* p) {
    uint32_t a;
    asm("{ .reg .u64 t; cvta.to.shared.u64 t, %1; cvt.u32.u64 %0, t; }" : "=r"(a) : "l"(p));
    return a;
}
__device__ __forceinline__ void ldmx4(uint32_t* r, uint32_t a) {
    asm volatile("ldmatrix.sync.aligned.m8n8.x4.shared.b16 {%0,%1,%2,%3}, [%4];"
                 : "=r"(r[0]), "=r"(r[1]), "=r"(r[2]), "=r"(r[3]) : "r"(a));
}
__device__ __forceinline__ void mma16816(float* d, const uint32_t* a, uint32_t b0, uint32_t b1) {
    asm volatile(
        "mma.sync.aligned.m16n8k16.row.col.f32.f16.f16.f32 "
        "{%0,%1,%2,%3}, {%4,%5,%6,%7}, {%8,%9}, {%0,%1,%2,%3};"
        : "+f"(d[0]), "+f"(d[1]), "+f"(d[2]), "+f"(d[3])
        : "r"(a[0]), "r"(a[1]), "r"(a[2]), "r"(a[3]), "r"(b0), "r"(b1));
}
__device__ __forceinline__ void cp16(uint32_t dst, const void* src) {
    asm volatile("cp.async.cg.shared.global [%0], [%1], 16;" :: "r"(dst), "l"(src));
}
#define CP_COMMIT() asm volatile("cp.async.commit_group;" ::: "memory")
#define CP_WAIT(n)  asm volatile("cp.async.wait_group %0;" :: "n"(n) : "memory")

// ---------------- prep kernel ----------------
__global__ void prep_kernel(
    const float* __restrict__ W0, const float* __restrict__ b0,
    const float* __restrict__ W1, const float* __restrict__ b1,
    const float* __restrict__ W2, const float* __restrict__ b2,
    const float* __restrict__ Wocc, const float* __restrict__ bocc,
    const float* __restrict__ Wc, const float* __restrict__ bc)
{
    const int idx = blockIdx.x * blockDim.x + threadIdx.x;
    const int stride = gridDim.x * blockDim.x;
    for (int i = idx; i < 256 * 320; i += stride) {
        const int n = i & 255;
        const int t = i >> 8;
        if (t < 32) {                                   // W0t [n][k<64]
            const int k = t * 2;
            const float v0 = (k < 63) ? W0[k * 256 + n] : 0.f;
            const float v1 = (k + 1 < 63) ? W0[(k + 1) * 256 + n] : 0.f;
            __half2 h = __floats2half2_rn(v0, v1);
            *(uint32_t*)(gW0t + (n * SW + k) * 2) = *(uint32_t*)&h;
        } else if (t < 64) {                            // W1bdT diag blocks
            const int k = (t - 32) * 2;
            const int base = (n >> 6) * 64;
            __half2 h = __floats2half2_rn(W1[(base + k) * 256 + n],
                                          W1[(base + k + 1) * 256 + n]);
            *(uint32_t*)(gW1bd + (n * SW + k) * 2) = *(uint32_t*)&h;
        } else if (t < 192) {                           // W1t chunked (k=128)
            const int k = (t - 64) * 2;
            const int c = k >> 7, kk = k & 127;
            __half2 h = __floats2half2_rn(W1[k * 256 + n], W1[(k + 1) * 256 + n]);
            *(uint32_t*)(gW1t + c * CHUNK_BYTES + (n * SC + kk) * 2) = *(uint32_t*)&h;
        } else {                                        // W2t chunked
            const int k = (t - 192) * 2;
            const int c = k >> 7, kk = k & 127;
            __half2 h = __floats2half2_rn(W2[k * 256 + n], W2[(k + 1) * 256 + n]);
            *(uint32_t*)(gW2t + c * CHUNK_BYTES + (n * SC + kk) * 2) = *(uint32_t*)&h;
        }
    }
    if (idx < 256) {
        gParams[PB0 + idx] = b0[idx];
        gParams[PB1 + idx] = b1[idx];
        gParams[PB2 + idx] = b2[idx];
        gParams[PWC + idx] = Wc[(idx >> 6) * 256 + idx];
        gParams[PWOCC + idx] = Wocc[idx];
    } else if (idx < 260) {
        gParams[PBC + idx - 256] = bc[idx - 256];
    } else if (idx == 260) {
        gParams[PBOCC] = bocc[0];
    }
}

// ---------------- warp GEMM: 64x64 tile ----------------
// acc[i][j2][q]: i = m16 group (4), j2 = n8 group (8), q = quad regs
template <int KSTEPS, bool ZERO>
__device__ __forceinline__ void run_gemm(float (&acc)[4][8][4],
                                         uint32_t aAddr, uint32_t aOff16,
                                         uint32_t bAddr, uint32_t bJ)
{
    if (ZERO) {
#pragma unroll
        for (int i = 0; i < 4; ++i)
#pragma unroll
            for (int j = 0; j < 8; ++j)
#pragma unroll
                for (int q = 0; q < 4; ++q) acc[i][j][q] = 0.f;
    }
#pragma unroll 2
    for (int ks = 0; ks < KSTEPS; ++ks) {
        uint32_t a[4][4], b[4][4];
#pragma unroll
        for (int i = 0; i < 4; ++i) ldmx4(a[i], aAddr + i * aOff16);
#pragma unroll
        for (int j = 0; j < 4; ++j) ldmx4(b[j], bAddr + j * bJ);
        aAddr += 32;
        bAddr += 32;
#pragma unroll
        for (int i = 0; i < 4; ++i)
#pragma unroll
            for (int j = 0; j < 4; ++j) {
                mma16816(acc[i][2 * j],     a[i], b[j][0], b[j][1]);
                mma16816(acc[i][2 * j + 1], a[i], b[j][2], b[j][3]);
            }
    }
}

// ---------------- main kernel ----------------
__global__ __launch_bounds__(THREADS, 1)
void mlp3d_mma(const float* __restrict__ coords,
               float* __restrict__ out_occ, float* __restrict__ out_cls, int npts)
{
    extern __shared__ unsigned char sm[];
    const uint32_t sb = smem_u32(sm);
    float* sPar = (float*)(sm + OFF_PAR);
    float* sOcc = (float*)(sm + OFF_OCC);

    const int tid = threadIdx.x;
    const int lane = tid & 31, wid = tid >> 5;
    const int wr = wid >> 2, wc = wid & 3;        // 2 row groups (64) x 4 col groups (64)
    const int gid = lane >> 2, tid4 = lane & 3;
    const int nbase = blockIdx.x * 128;

    // group A: W0t -> WB0 ; group B: W1bd -> WB1
    for (int i = tid * 16; i < SMALL_BYTES; i += THREADS * 16)
        cp16(sb + OFF_WB0 + i, gW0t + i);
    CP_COMMIT();
    for (int i = tid * 16; i < SMALL_BYTES; i += THREADS * 16)
        cp16(sb + OFF_WB1 + i, gW1bd + i);
    CP_COMMIT();

    // embed rows 0..127 (threads 0-127, E inside X region) || params (128-255)
    if (tid < 128) {
        const int n = nbase + tid;
        float c3[3] = {0.f, 0.f, 0.f};
        if (n < npts) {
            c3[0] = coords[n * 3 + 0];
            c3[1] = coords[n * 3 + 1];
            c3[2] = coords[n * 3 + 2];
        }
        __half* e = (__half*)(sm + OFF_X) + tid * SE;
        e[63] = __float2half_rn(0.f);
#pragma unroll
        for (int d = 0; d < 3; ++d) {
            e[d] = __float2half_rn(c3[d]);
            float s, co;
            sincosf(c3[d], &s, &co);
#pragma unroll
            for (int f = 0; f < 10; ++f) {
                e[3 + f * 6 + d] = __float2half_rn(s);
                e[6 + f * 6 + d] = __float2half_rn(co);
                const float s2 = 2.f * s * co;
                const float c2 = fmaf(-2.f * s, s, 1.f);
                s = s2; co = c2;
            }
        }
    } else {
        for (int i = tid - 128; i < NPAR; i += 128) sPar[i] = gParams[i];
    }
    CP_WAIT(1);          // A visible (B may pend)
    __syncthreads();

    // ldmatrix lane address components
    const int aRow = (lane & 7) + ((lane >> 3) & 1) * 8;
    const int aK   = ((lane >> 4) & 1) * 8;
    const int bRow = (lane & 7) + ((lane >> 4) & 1) * 8;
    const int bK   = ((lane >> 3) & 1) * 8;
    const uint32_t bW0 = sb + OFF_WB0 + ((wc * 64 + bRow) * SW + bK) * 2;
    const uint32_t bBD = sb + OFF_WB1 + ((wc * 64 + bRow) * SW + bK) * 2;
    const uint32_t bC0 = sb + OFF_WB0 + ((wc * 64 + bRow) * SC + bK) * 2;
    const uint32_t bC1 = sb + OFF_WB1 + ((wc * 64 + bRow) * SC + bK) * 2;
    const uint32_t bJs = 16 * SW * 2, bJc = 16 * SC * 2;

    const uint32_t aE = sb + OFF_X + ((wr * 64 + aRow) * SE + aK) * 2;
    const uint32_t aX = sb + OFF_X + ((wr * 64 + aRow) * SA + aK) * 2;
    const uint32_t aO16e = 16 * SE * 2, aO16 = 16 * SA * 2;

    float acc[4][8][4];

    // ================= P0: X = E @ W0t^T + b0 =================
    run_gemm<4, true>(acc, aE, aO16e, bW0, bJs);
    __syncthreads();                             // E reads done; WB0 dead
    // group C: W1t.c0 -> WB0
    for (int i = tid * 16; i < CHUNK_BYTES; i += THREADS * 16)
        cp16(sb + OFF_WB0 + i, gW1t + i);
    CP_COMMIT();
    {
        unsigned char* xB = sm + OFF_X;
#pragma unroll
        for (int rt = 0; rt < 4; ++rt) {
            const int r0 = wr * 64 + rt * 16 + gid;
#pragma unroll
            for (int ct = 0; ct < 8; ++ct) {
                const int c = wc * 64 + ct * 8 + tid4 * 2;
                const float bv0 = sPar[PB0 + c], bv1 = sPar[PB0 + c + 1];
                __half2 h0 = __floats2half2_rn(acc[rt][ct][0] + bv0, acc[rt][ct][1] + bv1);
                __half2 h1 = __floats2half2_rn(acc[rt][ct][2] + bv0, acc[rt][ct][3] + bv1);
                *(uint32_t*)(xB + (r0 * SA + c) * 2) = *(uint32_t*)&h0;
                *(uint32_t*)(xB + ((r0 + 8) * SA + c) * 2) = *(uint32_t*)&h1;
            }
        }
    }
    CP_WAIT(1);          // B visible (C pends)
    __syncthreads();     // X ready

    // ================= P1: part branches + class heads =================
    run_gemm<4, true>(acc, aX + wc * 64 * 2, aO16, bBD, bJs);
    {
        const int p = wc;
#pragma unroll
        for (int rt = 0; rt < 4; ++rt) {
            float s0 = 0.f, s1 = 0.f;
#pragma unroll
            for (int ct = 0; ct < 8; ++ct) {
                const int c = wc * 64 + ct * 8 + tid4 * 2;
                const float b0v = sPar[PB1 + c], b1v = sPar[PB1 + c + 1];
                const float w0v = sPar[PWC + c], w1v = sPar[PWC + c + 1];
                s0 = fmaf(fmaxf(acc[rt][ct][0] + b0v, 0.f), w0v, s0);
                s0 = fmaf(fmaxf(acc[rt][ct][1] + b1v, 0.f), w1v, s0);
                s1 = fmaf(fmaxf(acc[rt][ct][2] + b0v, 0.f), w0v, s1);
                s1 = fmaf(fmaxf(acc[rt][ct][3] + b1v, 0.f), w1v, s1);
            }
            s0 += __shfl_xor_sync(0xffffffffu, s0, 1);
            s0 += __shfl_xor_sync(0xffffffffu, s0, 2);
            s1 += __shfl_xor_sync(0xffffffffu, s1, 1);
            s1 += __shfl_xor_sync(0xffffffffu, s1, 2);
            if (tid4 == 0) {
                const float bcp = sPar[PBC + p];
                int n = nbase + wr * 64 + rt * 16 + gid;
                if (n < npts) out_cls[n * 4 + p] = s0 + bcp;
                n += 8;
                if (n < npts) out_cls[n * 4 + p] = s1 + bcp;
            }
        }
    }
    __syncthreads();     // WB1 (W1bd) dead
    // group D: W1t.c1 -> WB1
    for (int i = tid * 16; i < CHUNK_BYTES; i += THREADS * 16)
        cp16(sb + OFF_WB1 + i, gW1t + CHUNK_BYTES + i);
    CP_COMMIT();
    CP_WAIT(1);          // C visible (D pends)
    __syncthreads();

    // ================= P2: A1 = relu(X @ W1t + b1), 2 K-chunks =================
    run_gemm<8, true>(acc, aX, aO16, bC0, bJc);
    __syncthreads();     // WB0 dead
    // group E: W2t.c0 -> WB0
    for (int i = tid * 16; i < CHUNK_BYTES; i += THREADS * 16)
        cp16(sb + OFF_WB0 + i, gW2t + i);
    CP_COMMIT();
    CP_WAIT(1);          // D visible (E pends)
    __syncthreads();
    run_gemm<8, false>(acc, aX + 256, aO16, bC1, bJc);
    __syncthreads();     // WB1 dead; all X reads done
    // group F: W2t.c1 -> WB1
    for (int i = tid * 16; i < CHUNK_BYTES; i += THREADS * 16)
        cp16(sb + OFF_WB1 + i, gW2t + CHUNK_BYTES + i);
    CP_COMMIT();
    {   // epilogue: A1 -> X in place
        unsigned char* xB = sm + OFF_X;
#pragma unroll
        for (int rt = 0; rt < 4; ++rt) {
            const int r0 = wr * 64 + rt * 16 + gid;
#pragma unroll
            for (int ct = 0; ct < 8; ++ct) {
                const int c = wc * 64 + ct * 8 + tid4 * 2;
                const float bv0 = sPar[PB1 + c], bv1 = sPar[PB1 + c + 1];
                __half2 h0 = __floats2half2_rn(fmaxf(acc[rt][ct][0] + bv0, 0.f),
                                               fmaxf(acc[rt][ct][1] + bv1, 0.f));
                __half2 h1 = __floats2half2_rn(fmaxf(acc[rt][ct][2] + bv0, 0.f),
                                               fmaxf(acc[rt][ct][3] + bv1, 0.f));
                *(uint32_t*)(xB + (r0 * SA + c) * 2) = *(uint32_t*)&h0;
                *(uint32_t*)(xB + ((r0 + 8) * SA + c) * 2) = *(uint32_t*)&h1;
            }
        }
    }
    CP_WAIT(1);          // E visible (F pends)
    __syncthreads();     // A1 ready

    // ================= P3: occ, 2 K-chunks =================
    run_gemm<8, true>(acc, aX, aO16, bC0, bJc);
    CP_WAIT(0);          // F visible
    __syncthreads();
    run_gemm<8, false>(acc, aX + 256, aO16, bC1, bJc);
#pragma unroll
    for (int rt = 0; rt < 4; ++rt) {
        float s0 = 0.f, s1 = 0.f;
#pragma unroll
        for (int ct = 0; ct < 8; ++ct) {
            const int c = wc * 64 + ct * 8 + tid4 * 2;
            const float b0v = sPar[PB2 + c], b1v = sPar[PB2 + c + 1];
            const float w0v = sPar[PWOCC + c], w1v = sPar[PWOCC + c + 1];
            s0 = fmaf(fmaxf(acc[rt][ct][0] + b0v, 0.f), w0v, s0);
            s0 = fmaf(fmaxf(acc[rt][ct][1] + b1v, 0.f), w1v, s0);
            s1 = fmaf(fmaxf(acc[rt][ct][2] + b0v, 0.f), w0v, s1);
            s1 = fmaf(fmaxf(acc[rt][ct][3] + b1v, 0.f), w1v, s1);
        }
        s0 += __shfl_xor_sync(0xffffffffu, s0, 1);
        s0 += __shfl_xor_sync(0xffffffffu, s0, 2);
        s1 += __shfl_xor_sync(0xffffffffu, s1, 1);
        s1 += __shfl_xor_sync(0xffffffffu, s1, 2);
        if (tid4 == 0) {
            const int r = wr * 64 + rt * 16 + gid;
            sOcc[r * 4 + wc] = s0;
            sOcc[(r + 8) * 4 + wc] = s1;
        }
    }
    __syncthreads();
    if (tid < 128) {
        const float v = sOcc[tid * 4] + sOcc[tid * 4 + 1] + sOcc[tid * 4 + 2] +
                        sOcc[tid * 4 + 3] + sPar[PBOCC];
        const int n = nbase + tid;
        if (n < npts) out_occ[n] = v;
    }
}

// ---------------- launch ----------------
extern "C" void kernel_launch(void* const* d_in, const int* in_sizes, int n_in,
                              void* d_out, int out_size) {
    const float* coords = (const float*)d_in[0];
    const float* W0   = (const float*)d_in[1];
    const float* b0   = (const float*)d_in[2];
    const float* W1   = (const float*)d_in[3];
    const float* b1   = (const float*)d_in[4];
    const float* W2   = (const float*)d_in[5];
    const float* b2   = (const float*)d_in[6];
    const float* Wocc = (const float*)d_in[7];
    const float* bocc = (const float*)d_in[8];
    const float* Wc   = (const float*)d_in[9];
    const float* bc   = (const float*)d_in[10];

    const int npts = in_sizes[0] / 3;
    float* out_occ = (float*)d_out;
    float* out_cls = (float*)d_out + npts;

    prep_kernel<<<320, 256>>>(W0, b0, W1, b1, W2, b2, Wocc, bocc, Wc, bc);

    cudaFuncSetAttribute(mlp3d_mma, cudaFuncAttributeMaxDynamicSharedMemorySize, SMEM_BYTES);
    const int blocks = (npts + 127) / 128;
    mlp3d_mma<<<blocks, THREADS, SMEM_BYTES>>>(coords, out_occ, out_cls, npts);
}

// round 15
// speedup vs baseline: 1.4097x; 1.1376x over previous
#include <cuda_runtime.h>
#include <cuda_fp16.h>
#include <cstdint>

// MLP3D_final — mma.sync HMMA (f16 in / f32 acc), at the legacy-HMMA issue-rate
// ceiling (~16 cyc/SMSP per m16n8k16). This round removes MMA work instead of
// rescheduling it: the part branch is a K-chunk partial of GEMM1, so each warp
// runs GEMM1's four K=64 chunks in rotated order starting at its own column
// block; after chunk #1 the accumulator equals the part pre-activation and the
// class head is emitted mid-GEMM. P1 and the W1bd weight image are deleted.
//
// 128-pt blocks, 256 thr = 8 warps (2 row x 4 col), 64x64 warp tiles.
// All four W1t K-chunks resident simultaneously (144KB), then reused for W2t.
//   stage W0t->WB[0] || embed->E (inside X) || params
//   P0 : X = E @ W0t^T + b0      ; then stage W1t.c0..c3 -> WB[0..3]
//   G1 : acc = X @ W1t, chunks (wc, wc+1, wc+2, wc+3 mod 4);
//        after first chunk: class head for part wc from acc
//        epilogue: A1 = relu(acc + b1) -> X (in place); stage W2t.c0..c3
//   G2 : occ = relu(X @ W2t + b2) . Wocc

#define THREADS 256

// strides in f16 elements
#define SA 264   // activation rows (256 + 8 pad)
#define SE 72    // embedding rows (64 + 8 pad)
#define SW 72    // weight chunk rows (k=64 + 8 pad)

#define WCHUNK 36864                 // 256 * SW * 2 bytes per k=64 chunk

// smem byte offsets
#define OFF_WB  0                    // 4 chunks = 147456
#define OFF_X   147456               // 128 * SA * 2 = 67584
#define OFF_PAR 215040               // 1285 floats = 5140
#define OFF_OCC 220192               // 128*4*4 = 2048
#define SMEM_BYTES 222240

// param vector layout (floats)
#define PB0 0
#define PB1 256
#define PB2 512
#define PWC 768
#define PWOCC 1024
#define PBC 1280
#define PBOCC 1284
#define NPAR 1285

__device__ __align__(16) unsigned char gW0t[WCHUNK];
__device__ __align__(16) unsigned char gW1t[4 * WCHUNK];
__device__ __align__(16) unsigned char gW2t[4 * WCHUNK];
__device__ float gParams[NPAR];

// ---------------- PTX helpers ----------------
__device__ __forceinline__ uint32_t smem_u32(const void* p) {
    uint32_t a;
    asm("{ .reg .u64 t; cvta.to.shared.u64 t, %1; cvt.u32.u64 %0, t; }" : "=r"(a) : "l"(p));
    return a;
}
__device__ __forceinline__ void ldmx4(uint32_t* r, uint32_t a) {
    asm volatile("ldmatrix.sync.aligned.m8n8.x4.shared.b16 {%0,%1,%2,%3}, [%4];"
                 : "=r"(r[0]), "=r"(r[1]), "=r"(r[2]), "=r"(r[3]) : "r"(a));
}
__device__ __forceinline__ void mma16816(float* d, const uint32_t* a, uint32_t b0, uint32_t b1) {
    asm volatile(
        "mma.sync.aligned.m16n8k16.row.col.f32.f16.f16.f32 "
        "{%0,%1,%2,%3}, {%4,%5,%6,%7}, {%8,%9}, {%0,%1,%2,%3};"
        : "+f"(d[0]), "+f"(d[1]), "+f"(d[2]), "+f"(d[3])
        : "r"(a[0]), "r"(a[1]), "r"(a[2]), "r"(a[3]), "r"(b0), "r"(b1));
}
__device__ __forceinline__ void cp16(uint32_t dst, const void* src) {
    asm volatile("cp.async.cg.shared.global [%0], [%1], 16;" :: "r"(dst), "l"(src));
}
#define CP_COMMIT() asm volatile("cp.async.commit_group;" ::: "memory")
#define CP_WAIT(n)  asm volatile("cp.async.wait_group %0;" :: "n"(n) : "memory")

// ---------------- prep kernel ----------------
__global__ void prep_kernel(
    const float* __restrict__ W0, const float* __restrict__ b0,
    const float* __restrict__ W1, const float* __restrict__ b1,
    const float* __restrict__ W2, const float* __restrict__ b2,
    const float* __restrict__ Wocc, const float* __restrict__ bocc,
    const float* __restrict__ Wc, const float* __restrict__ bc)
{
    const int idx = blockIdx.x * blockDim.x + threadIdx.x;
    const int stride = gridDim.x * blockDim.x;
    for (int i = idx; i < 256 * 288; i += stride) {
        const int n = i & 255;
        const int t = i >> 8;
        if (t < 32) {                                   // W0t [n][k<64]
            const int k = t * 2;
            const float v0 = (k < 63) ? W0[k * 256 + n] : 0.f;
            const float v1 = (k + 1 < 63) ? W0[(k + 1) * 256 + n] : 0.f;
            __half2 h = __floats2half2_rn(v0, v1);
            *(uint32_t*)(gW0t + (n * SW + k) * 2) = *(uint32_t*)&h;
        } else if (t < 160) {                           // W1t, four k=64 chunks
            const int k = (t - 32) * 2;
            const int c = k >> 6, kk = k & 63;
            __half2 h = __floats2half2_rn(W1[k * 256 + n], W1[(k + 1) * 256 + n]);
            *(uint32_t*)(gW1t + c * WCHUNK + (n * SW + kk) * 2) = *(uint32_t*)&h;
        } else {                                        // W2t, four k=64 chunks
            const int k = (t - 160) * 2;
            const int c = k >> 6, kk = k & 63;
            __half2 h = __floats2half2_rn(W2[k * 256 + n], W2[(k + 1) * 256 + n]);
            *(uint32_t*)(gW2t + c * WCHUNK + (n * SW + kk) * 2) = *(uint32_t*)&h;
        }
    }
    if (idx < 256) {
        gParams[PB0 + idx] = b0[idx];
        gParams[PB1 + idx] = b1[idx];
        gParams[PB2 + idx] = b2[idx];
        gParams[PWC + idx] = Wc[(idx >> 6) * 256 + idx];
        gParams[PWOCC + idx] = Wocc[idx];
    } else if (idx < 260) {
        gParams[PBC + idx - 256] = bc[idx - 256];
    } else if (idx == 260) {
        gParams[PBOCC] = bocc[0];
    }
}

// ---------------- warp GEMM: 64x64 tile, K=64 (4 ksteps) ----------------
template <bool ZERO>
__device__ __forceinline__ void run_gemm64(float (&acc)[4][8][4],
                                           uint32_t aAddr, uint32_t aOff16,
                                           uint32_t bAddr)
{
    if (ZERO) {
#pragma unroll
        for (int i = 0; i < 4; ++i)
#pragma unroll
            for (int j = 0; j < 8; ++j)
#pragma unroll
                for (int q = 0; q < 4; ++q) acc[i][j][q] = 0.f;
    }
#pragma unroll
    for (int ks = 0; ks < 4; ++ks) {
        uint32_t a[4][4], b[4][4];
#pragma unroll
        for (int i = 0; i < 4; ++i) ldmx4(a[i], aAddr + i * aOff16);
#pragma unroll
        for (int j = 0; j < 4; ++j) ldmx4(b[j], bAddr + j * (16 * SW * 2));
        aAddr += 32;
        bAddr += 32;
#pragma unroll
        for (int i = 0; i < 4; ++i)
#pragma unroll
            for (int j = 0; j < 4; ++j) {
                mma16816(acc[i][2 * j],     a[i], b[j][0], b[j][1]);
                mma16816(acc[i][2 * j + 1], a[i], b[j][2], b[j][3]);
            }
    }
}

// ---------------- main kernel ----------------
__global__ __launch_bounds__(THREADS, 1)
void mlp3d_mma(const float* __restrict__ coords,
               float* __restrict__ out_occ, float* __restrict__ out_cls, int npts)
{
    extern __shared__ unsigned char sm[];
    const uint32_t sb = smem_u32(sm);
    float* sPar = (float*)(sm + OFF_PAR);
    float* sOcc = (float*)(sm + OFF_OCC);

    const int tid = threadIdx.x;
    const int lane = tid & 31, wid = tid >> 5;
    const int wr = wid >> 2, wc = wid & 3;        // 2 row groups (64) x 4 col groups (64)
    const int gid = lane >> 2, tid4 = lane & 3;
    const int nbase = blockIdx.x * 128;

    // stage W0t -> WB[0]
    for (int i = tid * 16; i < WCHUNK; i += THREADS * 16)
        cp16(sb + OFF_WB + i, gW0t + i);
    CP_COMMIT();

    // embed rows 0..127 (threads 0-127, E inside X region) || params (128-255)
    if (tid < 128) {
        const int n = nbase + tid;
        float c3[3] = {0.f, 0.f, 0.f};
        if (n < npts) {
            c3[0] = coords[n * 3 + 0];
            c3[1] = coords[n * 3 + 1];
            c3[2] = coords[n * 3 + 2];
        }
        __half* e = (__half*)(sm + OFF_X) + tid * SE;
        e[63] = __float2half_rn(0.f);
#pragma unroll
        for (int d = 0; d < 3; ++d) {
            e[d] = __float2half_rn(c3[d]);
            float s, co;
            sincosf(c3[d], &s, &co);
#pragma unroll
            for (int f = 0; f < 10; ++f) {
                e[3 + f * 6 + d] = __float2half_rn(s);
                e[6 + f * 6 + d] = __float2half_rn(co);
                const float s2 = 2.f * s * co;
                const float c2 = fmaf(-2.f * s, s, 1.f);
                s = s2; co = c2;
            }
        }
    } else {
        for (int i = tid - 128; i < NPAR; i += 128) sPar[i] = gParams[i];
    }
    CP_WAIT(0);
    __syncthreads();

    // ldmatrix lane address components
    const int aRow = (lane & 7) + ((lane >> 3) & 1) * 8;
    const int aK   = ((lane >> 4) & 1) * 8;
    const int bRow = (lane & 7) + ((lane >> 4) & 1) * 8;
    const int bK   = ((lane >> 3) & 1) * 8;
    const uint32_t bWB = sb + OFF_WB + ((wc * 64 + bRow) * SW + bK) * 2;

    const uint32_t aE = sb + OFF_X + ((wr * 64 + aRow) * SE + aK) * 2;
    const uint32_t aX = sb + OFF_X + ((wr * 64 + aRow) * SA + aK) * 2;
    const uint32_t aO16e = 16 * SE * 2, aO16 = 16 * SA * 2;

    float acc[4][8][4];

    // ================= P0: X = E @ W0t^T + b0 =================
    run_gemm64<true>(acc, aE, aO16e, bWB);
    __syncthreads();                             // E + W0t reads done
    // stage W1t chunks 0..3 -> WB[0..3]
    for (int i = tid * 16; i < 4 * WCHUNK; i += THREADS * 16)
        cp16(sb + OFF_WB + i, gW1t + i);
    CP_COMMIT();
    {
        unsigned char* xB = sm + OFF_X;
#pragma unroll
        for (int rt = 0; rt < 4; ++rt) {
            const int r0 = wr * 64 + rt * 16 + gid;
#pragma unroll
            for (int ct = 0; ct < 8; ++ct) {
                const int c = wc * 64 + ct * 8 + tid4 * 2;
                const float bv0 = sPar[PB0 + c], bv1 = sPar[PB0 + c + 1];
                __half2 h0 = __floats2half2_rn(acc[rt][ct][0] + bv0, acc[rt][ct][1] + bv1);
                __half2 h1 = __floats2half2_rn(acc[rt][ct][2] + bv0, acc[rt][ct][3] + bv1);
                *(uint32_t*)(xB + (r0 * SA + c) * 2) = *(uint32_t*)&h0;
                *(uint32_t*)(xB + ((r0 + 8) * SA + c) * 2) = *(uint32_t*)&h1;
            }
        }
    }
    CP_WAIT(0);
    __syncthreads();     // X ready + W1t resident

    // ================= G1: trunk GEMM1 with fused part branch =================
    // chunk order (wc, wc+1, wc+2, wc+3 mod 4); after first chunk acc holds the
    // part-branch pre-activation for part wc (rows wr*64.., cols wc*64..).
    run_gemm64<true>(acc, aX + wc * 128, aO16, bWB + wc * WCHUNK);
    {   // class head for part p = wc (reads acc only; acc preserved)
        const int p = wc;
#pragma unroll
        for (int rt = 0; rt < 4; ++rt) {
            float s0 = 0.f, s1 = 0.f;
#pragma unroll
            for (int ct = 0; ct < 8; ++ct) {
                const int c = wc * 64 + ct * 8 + tid4 * 2;
                const float b0v = sPar[PB1 + c], b1v = sPar[PB1 + c + 1];
                const float w0v = sPar[PWC + c], w1v = sPar[PWC + c + 1];
                s0 = fmaf(fmaxf(acc[rt][ct][0] + b0v, 0.f), w0v, s0);
                s0 = fmaf(fmaxf(acc[rt][ct][1] + b1v, 0.f), w1v, s0);
                s1 = fmaf(fmaxf(acc[rt][ct][2] + b0v, 0.f), w0v, s1);
                s1 = fmaf(fmaxf(acc[rt][ct][3] + b1v, 0.f), w1v, s1);
            }
            s0 += __shfl_xor_sync(0xffffffffu, s0, 1);
            s0 += __shfl_xor_sync(0xffffffffu, s0, 2);
            s1 += __shfl_xor_sync(0xffffffffu, s1, 1);
            s1 += __shfl_xor_sync(0xffffffffu, s1, 2);
            if (tid4 == 0) {
                const float bcp = sPar[PBC + p];
                int n = nbase + wr * 64 + rt * 16 + gid;
                if (n < npts) out_cls[n * 4 + p] = s0 + bcp;
                n += 8;
                if (n < npts) out_cls[n * 4 + p] = s1 + bcp;
            }
        }
    }
#pragma unroll
    for (int t = 1; t < 4; ++t) {
        const int c = (wc + t) & 3;
        run_gemm64<false>(acc, aX + c * 128, aO16, bWB + c * WCHUNK);
    }
    __syncthreads();     // all X + W1t reads done
    // stage W2t chunks 0..3 -> WB[0..3]
    for (int i = tid * 16; i < 4 * WCHUNK; i += THREADS * 16)
        cp16(sb + OFF_WB + i, gW2t + i);
    CP_COMMIT();
    {   // epilogue: A1 = relu(acc + b1) -> X in place
        unsigned char* xB = sm + OFF_X;
#pragma unroll
        for (int rt = 0; rt < 4; ++rt) {
            const int r0 = wr * 64 + rt * 16 + gid;
#pragma unroll
            for (int ct = 0; ct < 8; ++ct) {
                const int c = wc * 64 + ct * 8 + tid4 * 2;
                const float bv0 = sPar[PB1 + c], bv1 = sPar[PB1 + c + 1];
                __half2 h0 = __floats2half2_rn(fmaxf(acc[rt][ct][0] + bv0, 0.f),
                                               fmaxf(acc[rt][ct][1] + bv1, 0.f));
                __half2 h1 = __floats2half2_rn(fmaxf(acc[rt][ct][2] + bv0, 0.f),
                                               fmaxf(acc[rt][ct][3] + bv1, 0.f));
                *(uint32_t*)(xB + (r0 * SA + c) * 2) = *(uint32_t*)&h0;
                *(uint32_t*)(xB + ((r0 + 8) * SA + c) * 2) = *(uint32_t*)&h1;
            }
        }
    }
    CP_WAIT(0);
    __syncthreads();     // A1 ready + W2t resident

    // ================= G2: occ = relu(A1 @ W2t + b2) . Wocc =================
    run_gemm64<true>(acc, aX, aO16, bWB);
#pragma unroll
    for (int t = 1; t < 4; ++t)
        run_gemm64<false>(acc, aX + t * 128, aO16, bWB + t * WCHUNK);
#pragma unroll
    for (int rt = 0; rt < 4; ++rt) {
        float s0 = 0.f, s1 = 0.f;
#pragma unroll
        for (int ct = 0; ct < 8; ++ct) {
            const int c = wc * 64 + ct * 8 + tid4 * 2;
            const float b0v = sPar[PB2 + c], b1v = sPar[PB2 + c + 1];
            const float w0v = sPar[PWOCC + c], w1v = sPar[PWOCC + c + 1];
            s0 = fmaf(fmaxf(acc[rt][ct][0] + b0v, 0.f), w0v, s0);
            s0 = fmaf(fmaxf(acc[rt][ct][1] + b1v, 0.f), w1v, s0);
            s1 = fmaf(fmaxf(acc[rt][ct][2] + b0v, 0.f), w0v, s1);
            s1 = fmaf(fmaxf(acc[rt][ct][3] + b1v, 0.f), w1v, s1);
        }
        s0 += __shfl_xor_sync(0xffffffffu, s0, 1);
        s0 += __shfl_xor_sync(0xffffffffu, s0, 2);
        s1 += __shfl_xor_sync(0xffffffffu, s1, 1);
        s1 += __shfl_xor_sync(0xffffffffu, s1, 2);
        if (tid4 == 0) {
            const int r = wr * 64 + rt * 16 + gid;
            sOcc[r * 4 + wc] = s0;
            sOcc[(r + 8) * 4 + wc] = s1;
        }
    }
    __syncthreads();
    if (tid < 128) {
        const float v = sOcc[tid * 4] + sOcc[tid * 4 + 1] + sOcc[tid * 4 + 2] +
                        sOcc[tid * 4 + 3] + sPar[PBOCC];
        const int n = nbase + tid;
        if (n < npts) out_occ[n] = v;
    }
}

// ---------------- launch ----------------
extern "C" void kernel_launch(void* const* d_in, const int* in_sizes, int n_in,
                              void* d_out, int out_size) {
    const float* coords = (const float*)d_in[0];
    const float* W0   = (const float*)d_in[1];
    const float* b0   = (const float*)d_in[2];
    const float* W1   = (const float*)d_in[3];
    const float* b1   = (const float*)d_in[4];
    const float* W2   = (const float*)d_in[5];
    const float* b2   = (const float*)d_in[6];
    const float* Wocc = (const float*)d_in[7];
    const float* bocc = (const float*)d_in[8];
    const float* Wc   = (const float*)d_in[9];
    const float* bc   = (const float*)d_in[10];

    const int npts = in_sizes[0] / 3;
    float* out_occ = (float*)d_out;
    float* out_cls = (float*)d_out + npts;

    prep_kernel<<<320, 256>>>(W0, b0, W1, b1, W2, b2, Wocc, bocc, Wc, bc);

    cudaFuncSetAttribute(mlp3d_mma, cudaFuncAttributeMaxDynamicSharedMemorySize, SMEM_BYTES);
    const int blocks = (npts + 127) / 128;
    mlp3d_mma<<<blocks, THREADS, SMEM_BYTES>>>(coords, out_occ, out_cls, npts);
}